// round 2
// baseline (speedup 1.0000x reference)
#include <cuda_runtime.h>

#define NB   256      // batches
#define NQ   1000     // queries
#define NC   80       // classes
#define QC   80000    // NQ*NC
#define K    300      // top-k
#define CAP  4096     // candidate buffer capacity
#define NTH  512
#define NV   (QC/4)   // 20000 float4 per batch

// order-preserving float -> uint key (larger key == larger float)
__device__ __forceinline__ unsigned key_of(float x) {
    unsigned u = __float_as_uint(x);
    return (u & 0x80000000u) ? ~u : (u | 0x80000000u);
}
__device__ __forceinline__ float val_of(unsigned k) {
    unsigned u = (k & 0x80000000u) ? (k ^ 0x80000000u) : ~k;
    return __uint_as_float(u);
}

__global__ __launch_bounds__(NTH)
void rtdetr_topk_kernel(const float* __restrict__ logits,
                        const float* __restrict__ boxes,
                        const float* __restrict__ sizes,
                        float* __restrict__ out)
{
    __shared__ unsigned long long cand[CAP];
    __shared__ unsigned s_cnt;

    const int b   = blockIdx.x;
    const int tid = threadIdx.x;
    const unsigned lane = tid & 31;
    const float4* base = (const float4*)(logits + (size_t)b * QC);

    // ---- single-pass threshold compaction, with key-space bisection fallback ----
    unsigned lo_key = 0u, hi_key = 0xFFFFFFFFu;
    unsigned cur = key_of(2.0f);   // P(N(0,1) > 2) ~ 2.3% -> ~1820 candidates
    unsigned M = 0;

    for (int attempt = 0; attempt < 32; attempt++) {
        if (tid == 0) s_cnt = 0;
        __syncthreads();
        const float t = val_of(cur);

        #pragma unroll 4
        for (int i = tid; i < NV; i += NTH) {
            float4 v = base[i];
            float xs[4] = {v.x, v.y, v.z, v.w};
            #pragma unroll
            for (int j = 0; j < 4; j++) {
                bool pred = (xs[j] > t);
                unsigned mask = __ballot_sync(0xFFFFFFFFu, pred);
                if (mask) {
                    int leader = __ffs(mask) - 1;
                    unsigned boff = 0;
                    if ((int)lane == leader)
                        boff = atomicAdd(&s_cnt, (unsigned)__popc(mask));
                    boff = __shfl_sync(0xFFFFFFFFu, boff, leader);
                    if (pred) {
                        unsigned p = boff + __popc(mask & ((1u << lane) - 1u));
                        if (p < CAP) {
                            unsigned idx = 4u * (unsigned)i + (unsigned)j;
                            cand[p] = ((unsigned long long)key_of(xs[j]) << 32)
                                    | (unsigned long long)(~idx);
                        }
                    }
                }
            }
        }
        __syncthreads();
        M = s_cnt;
        if (M >= K && M <= CAP) break;
        // bisect threshold in key space (monotone); rescans hit L2
        if (M < K) { hi_key = cur; cur = lo_key + ((cur - lo_key) >> 1); }
        else       { lo_key = cur; cur = cur + ((hi_key - cur) >> 1); }
        __syncthreads();
    }
    if (M > CAP) M = CAP;

    // ---- pad to pow2, bitonic sort descending (composite = key<<32 | ~idx) ----
    unsigned n = 512;
    while (n < M) n <<= 1;          // <= 4096
    for (unsigned i = M + tid; i < n; i += NTH) cand[i] = 0ull;
    __syncthreads();

    for (unsigned kk = 2; kk <= n; kk <<= 1) {
        for (unsigned j = kk >> 1; j > 0; j >>= 1) {
            for (unsigned i = tid; i < n; i += NTH) {
                unsigned l = i ^ j;
                if (l > i) {
                    unsigned long long a = cand[i];
                    unsigned long long c = cand[l];
                    bool desc = ((i & kk) == 0);
                    if (desc ? (a < c) : (a > c)) {
                        cand[i] = c; cand[l] = a;
                    }
                }
            }
            __syncthreads();
        }
    }

    // ---- epilogue: top K -> labels, boxes, scores ----
    if (tid < K) {
        unsigned long long comp = cand[tid];
        unsigned kk  = (unsigned)(comp >> 32);
        unsigned idx = ~(unsigned)comp;
        float x = val_of(kk);
        float score = 1.0f / (1.0f + expf(-x));
        int label = (int)(idx % NC);
        int q     = (int)(idx / NC);

        float4 bx = ((const float4*)(boxes + ((size_t)b * NQ + q) * 4))[0];
        float w = sizes[2 * b], h = sizes[2 * b + 1];
        float hw = 0.5f * bx.z, hh = 0.5f * bx.w;

        int o = b * K + tid;
        out[o] = (float)label;                     // labels [B,K]
        float* ob = out + NB * K + (size_t)o * 4;  // boxes  [B,K,4]
        ob[0] = (bx.x - hw) * w;
        ob[1] = (bx.y - hh) * h;
        ob[2] = (bx.x + hw) * w;
        ob[3] = (bx.y + hh) * h;
        out[(size_t)NB * K * 5 + o] = score;       // scores [B,K]
    }
}

extern "C" void kernel_launch(void* const* d_in, const int* in_sizes, int n_in,
                              void* d_out, int out_size) {
    const float* logits = (const float*)d_in[0];
    const float* boxes  = (const float*)d_in[1];
    const float* sizes  = (const float*)d_in[2];
    float* out = (float*)d_out;
    rtdetr_topk_kernel<<<NB, NTH>>>(logits, boxes, sizes, out);
}

// round 6
// speedup vs baseline: 1.9940x; 1.9940x over previous
#include <cuda_runtime.h>

#define NB    256      // batches
#define NQ    1000     // queries
#define NC    80       // classes
#define QC    80000    // NQ*NC
#define K     300      // top-k
#define NTH   512
#define NWARP 16
#define CAP_W 128                 // per-warp candidate slots
#define CAPT  (NWARP * CAP_W)     // 2048 total
#define NV    (QC / 4)            // 20000 float4 per batch

// order-preserving float -> uint key (larger key == larger float)
__device__ __forceinline__ unsigned key_of(float x) {
    unsigned u = __float_as_uint(x);
    return (u & 0x80000000u) ? ~u : (u | 0x80000000u);
}
__device__ __forceinline__ float val_of(unsigned k) {
    unsigned u = (k & 0x80000000u) ? (k ^ 0x80000000u) : ~k;
    return __uint_as_float(u);
}

__global__ __launch_bounds__(NTH)
void rtdetr_topk_kernel(const float* __restrict__ logits,
                        const float* __restrict__ boxes,
                        const float* __restrict__ sizes,
                        float* __restrict__ out)
{
    __shared__ unsigned long long cand[CAPT];
    __shared__ unsigned wcnt[NWARP];
    __shared__ unsigned soff[NWARP + 1];
    __shared__ unsigned s_total;
    __shared__ int      s_ovf;

    const int b    = blockIdx.x;
    const int tid  = threadIdx.x;
    const int wid  = tid >> 5;
    const int lane = tid & 31;
    const float4* base = (const float4*)(logits + (size_t)b * QC);

    // ---- scan with fixed threshold; bisection fallback in key space ----
    unsigned lo_key = 0u, hi_key = 0xFFFFFFFFu;
    unsigned cur = key_of(2.45f);   // P(N(0,1)>2.45) ~ 0.71% -> ~571 cands/batch
    unsigned M = 0;

    for (int attempt = 0; attempt < 32; attempt++) {
        if (tid < NWARP) wcnt[tid] = 0;
        if (tid == 0) { s_total = 0; s_ovf = 0; }
        __syncthreads();
        const float t = val_of(cur);

        #pragma unroll 2
        for (int i = tid; i < NV; i += NTH) {
            float4 v = base[i];
            float m01 = fmaxf(v.x, v.y);
            float m23 = fmaxf(v.z, v.w);
            if (fmaxf(m01, m23) > t) {               // rare (~2.8% of iters)
                float xs[4] = {v.x, v.y, v.z, v.w};
                #pragma unroll
                for (int j = 0; j < 4; j++) {
                    if (xs[j] > t) {
                        unsigned p = atomicAdd(&wcnt[wid], 1u);
                        if (p < CAP_W) {
                            unsigned idx = 4u * (unsigned)i + (unsigned)j;
                            cand[wid * CAP_W + p] =
                                ((unsigned long long)key_of(xs[j]) << 32)
                              | (unsigned long long)(~idx);
                        }
                    }
                }
            }
        }
        __syncthreads();

        if (tid == 0) {
            unsigned s = 0; int ovf = 0;
            #pragma unroll
            for (int w = 0; w < NWARP; w++) {
                if (wcnt[w] > CAP_W) ovf = 1;
                s += min(wcnt[w], (unsigned)CAP_W);
            }
            s_total = s; s_ovf = ovf;
        }
        __syncthreads();
        M = s_total;
        int ovf = s_ovf;
        if (!ovf && M >= K && M <= CAPT) break;
        // bisect monotone key space: too many -> raise threshold, too few -> lower
        if (ovf || M > CAPT) { lo_key = cur; cur = cur + ((hi_key - cur) >> 1); }
        else                 { hi_key = cur; cur = lo_key + ((cur - lo_key) >> 1); }
        __syncthreads();
    }

    // ---- compact per-warp slices (register-staged to avoid overlap races) ----
    if (tid == 0) {
        unsigned s = 0;
        #pragma unroll
        for (int w = 0; w < NWARP; w++) {
            soff[w] = s;
            s += min(wcnt[w], (unsigned)CAP_W);
        }
        soff[NWARP] = s;
    }
    __syncthreads();
    {
        unsigned cnt = min(wcnt[wid], (unsigned)CAP_W);
        unsigned long long rr[CAP_W / 32];
        #pragma unroll
        for (int k = 0; k < CAP_W / 32; k++) {
            unsigned s = (unsigned)lane + 32u * k;
            if (s < cnt) rr[k] = cand[wid * CAP_W + s];
        }
        __syncthreads();
        unsigned dst = soff[wid];
        #pragma unroll
        for (int k = 0; k < CAP_W / 32; k++) {
            unsigned s = (unsigned)lane + 32u * k;
            if (s < cnt) cand[dst + s] = rr[k];
        }
    }
    M = soff[NWARP];

    // ---- pad to pow2, bitonic sort descending (composite = key<<32 | ~idx) ----
    unsigned n = 512;
    while (n < M) n <<= 1;          // <= 2048
    for (unsigned i = M + tid; i < n; i += NTH) cand[i] = 0ull;
    __syncthreads();

    for (unsigned kk = 2; kk <= n; kk <<= 1) {
        for (unsigned j = kk >> 1; j > 0; j >>= 1) {
            for (unsigned i = tid; i < n; i += NTH) {
                unsigned l = i ^ j;
                if (l > i) {
                    unsigned long long a = cand[i];
                    unsigned long long c = cand[l];
                    bool desc = ((i & kk) == 0);
                    if (desc ? (a < c) : (a > c)) {
                        cand[i] = c; cand[l] = a;
                    }
                }
            }
            __syncthreads();
        }
    }

    // ---- epilogue: top K -> labels, boxes, scores ----
    if (tid < K) {
        unsigned long long comp = cand[tid];
        unsigned kk  = (unsigned)(comp >> 32);
        unsigned idx = ~(unsigned)comp;
        float x = val_of(kk);
        float score = 1.0f / (1.0f + expf(-x));
        int label = (int)(idx % NC);
        int q     = (int)(idx / NC);

        float4 bx = ((const float4*)(boxes + ((size_t)b * NQ + q) * 4))[0];
        float w = sizes[2 * b], h = sizes[2 * b + 1];
        float hw = 0.5f * bx.z, hh = 0.5f * bx.w;

        int o = b * K + tid;
        out[o] = (float)label;                     // labels [B,K]
        float* ob = out + NB * K + (size_t)o * 4;  // boxes  [B,K,4]
        ob[0] = (bx.x - hw) * w;
        ob[1] = (bx.y - hh) * h;
        ob[2] = (bx.x + hw) * w;
        ob[3] = (bx.y + hh) * h;
        out[(size_t)NB * K * 5 + o] = score;       // scores [B,K]
    }
}

extern "C" void kernel_launch(void* const* d_in, const int* in_sizes, int n_in,
                              void* d_out, int out_size) {
    const float* logits = (const float*)d_in[0];
    const float* boxes  = (const float*)d_in[1];
    const float* sizes  = (const float*)d_in[2];
    float* out = (float*)d_out;
    rtdetr_topk_kernel<<<NB, NTH>>>(logits, boxes, sizes, out);
}